// round 7
// baseline (speedup 1.0000x reference)
#include <cuda_runtime.h>
#include <math.h>

// Problem constants
#define Nn 50000
#define Ee 800000
#define IND 9
#define HIDD 128
#define Gg 256
#define OUTD 10
#define CLUST 20
#define EPSv 1e-5f

// ---------------- scratch (device globals; no allocation allowed) ----------------
__device__ float g_h[Nn * HIDD];        // GEMM output (pre-aggregation)
__device__ float g_act[Nn * HIDD];      // rational output (pre-BN)
__device__ int   g_cnt[Nn];
__device__ int   g_cursor[Nn];
__device__ int   g_rowptr[Nn + 1];
__device__ int   g_csr[2 * Ee];         // packed per sorted edge: (src, bits(dinv[src]))
__device__ float g_dinv[Nn];
__device__ float g_t[Nn];
__device__ float g_sum[HIDD];
__device__ float g_sq[HIDD];
__device__ float g_a[HIDD];
__device__ float g_c[HIDD];
__device__ float g_Wa[HIDD * HIDD];
__device__ float g_r[HIDD];
__device__ int   g_gstart[Gg + 1];
__device__ float g_pooled[Gg * HIDD];
__device__ float g_z1[Gg * HIDD];
__device__ float g_z2[Gg * HIDD];

// ---------------- precompute kernels ----------------
__global__ void init_kernel() {
    int i = blockIdx.x * blockDim.x + threadIdx.x;
    if (i < Nn) { g_cnt[i] = 0; g_cursor[i] = 0; }
    if (i < HIDD) { g_sum[i] = 0.f; g_sq[i] = 0.f; }
}

__global__ void hist_kernel(const int* __restrict__ ei) {
    int e = blockIdx.x * blockDim.x + threadIdx.x;
    if (e < Ee) atomicAdd(&g_cnt[ei[Ee + e]], 1);
}

// single-block exclusive scan of g_cnt -> g_rowptr
__global__ void scan_kernel() {
    __shared__ int ssum[1024];
    const int ITEMS = 49; // 1024*49 >= 50000
    int t = threadIdx.x;
    int base = t * ITEMS;
    int s = 0;
    for (int i = 0; i < ITEMS; i++) { int idx = base + i; if (idx < Nn) s += g_cnt[idx]; }
    ssum[t] = s; __syncthreads();
    for (int off = 1; off < 1024; off <<= 1) {
        int v = (t >= off) ? ssum[t - off] : 0;
        __syncthreads();
        ssum[t] += v;
        __syncthreads();
    }
    int run = ssum[t] - s; // exclusive prefix
    for (int i = 0; i < ITEMS; i++) {
        int idx = base + i;
        if (idx < Nn) { g_rowptr[idx] = run; run += g_cnt[idx]; }
    }
    if (t == 0) g_rowptr[Nn] = Ee;
}

__global__ void dinv_kernel() {
    int i = blockIdx.x * blockDim.x + threadIdx.x;
    if (i < Nn) g_dinv[i] = rsqrtf((float)g_cnt[i] + 1.0f);
}

__global__ void fill_kernel(const int* __restrict__ ei) {
    int e = blockIdx.x * blockDim.x + threadIdx.x;
    if (e < Ee) {
        int d = ei[Ee + e];
        int pos = g_rowptr[d] + atomicAdd(&g_cursor[d], 1);
        g_csr[2 * pos] = ei[e]; // src
    }
}

__global__ void pack_kernel() {
    int e = blockIdx.x * blockDim.x + threadIdx.x;
    if (e < Ee) {
        int s = g_csr[2 * e];
        g_csr[2 * e + 1] = __float_as_int(g_dinv[s]);
    }
}

// t[v] = dinv[v] * sum_in dinv[src] + dinv[v]^2  (warp per node)
__global__ void tfac_kernel() {
    int w = (blockIdx.x * blockDim.x + threadIdx.x) >> 5;
    int lane = threadIdx.x & 31;
    if (w >= Nn) return;
    int beg = g_rowptr[w], end = g_rowptr[w + 1];
    float s = 0.f;
    for (int e = beg + lane; e < end; e += 32) s += __int_as_float(g_csr[2 * e + 1]);
    #pragma unroll
    for (int o = 16; o; o >>= 1) s += __shfl_xor_sync(0xffffffffu, s, o);
    if (lane == 0) {
        float dv = g_dinv[w];
        g_t[w] = dv * s + dv * dv;
    }
}

// ---------------- GEMM layer 0: h = x(N,9) @ W0(9,128) ----------------
__global__ void gemm0_kernel(const float* __restrict__ x, const float* __restrict__ W0) {
    __shared__ float sW[IND * HIDD];
    for (int i = threadIdx.x; i < IND * HIDD; i += blockDim.x) sW[i] = W0[i];
    __syncthreads();
    int j = threadIdx.x & 127;
    int rpb = blockDim.x >> 7; // 2
    int r0 = blockIdx.x * rpb + (threadIdx.x >> 7);
    for (int n = r0; n < Nn; n += gridDim.x * rpb) {
        float acc = 0.f;
        #pragma unroll
        for (int k = 0; k < IND; k++) acc = fmaf(x[n * IND + k], sW[k * HIDD + j], acc);
        g_h[n * HIDD + j] = acc;
    }
}

// ---------------- SGEMM: g_h = g_act(N,128) @ g_Wa(128,128) ----------------
#define GBK 32
__global__ __launch_bounds__(256, 2) void gemm_kernel() {
    __shared__ float Ast[GBK * 132]; // transposed A chunk [k][row], pad 132
    __shared__ float Ws[GBK * 128];  // B chunk [k][j]
    int tid = threadIdx.x;
    int blockRow = blockIdx.x * 128;
    int tx = tid & 15, ty = tid >> 4;
    int ro = ty * 8, co = tx * 8;
    float acc[8][8] = {{0.f}};
    for (int kc = 0; kc < 128; kc += GBK) {
        #pragma unroll
        for (int i = 0; i < 4; i++) {
            int v = tid + i * 256;       // [0,1024)
            int row = v >> 3, kq = v & 7;
            int grow = blockRow + row;
            float4 val = make_float4(0.f, 0.f, 0.f, 0.f);
            if (grow < Nn) val = *(const float4*)&g_act[grow * 128 + kc + kq * 4];
            Ast[(kq * 4 + 0) * 132 + row] = val.x;
            Ast[(kq * 4 + 1) * 132 + row] = val.y;
            Ast[(kq * 4 + 2) * 132 + row] = val.z;
            Ast[(kq * 4 + 3) * 132 + row] = val.w;
        }
        #pragma unroll
        for (int i = 0; i < 4; i++) {
            int v = tid + i * 256;
            int kk = v >> 5, jq = v & 31;
            *(float4*)&Ws[kk * 128 + jq * 4] = *(const float4*)&g_Wa[(kc + kk) * 128 + jq * 4];
        }
        __syncthreads();
        #pragma unroll
        for (int kk = 0; kk < GBK; kk++) {
            float a[8], b[8];
            *(float4*)(a)     = *(float4*)&Ast[kk * 132 + ro];
            *(float4*)(a + 4) = *(float4*)&Ast[kk * 132 + ro + 4];
            *(float4*)(b)     = *(float4*)&Ws[kk * 128 + co];
            *(float4*)(b + 4) = *(float4*)&Ws[kk * 128 + co + 4];
            #pragma unroll
            for (int i2 = 0; i2 < 8; i2++)
                #pragma unroll
                for (int j2 = 0; j2 < 8; j2++)
                    acc[i2][j2] = fmaf(a[i2], b[j2], acc[i2][j2]);
        }
        __syncthreads();
    }
    #pragma unroll
    for (int i2 = 0; i2 < 8; i2++) {
        int grow = blockRow + ro + i2;
        if (grow < Nn) {
            *(float4*)&g_h[grow * 128 + co]     = make_float4(acc[i2][0], acc[i2][1], acc[i2][2], acc[i2][3]);
            *(float4*)&g_h[grow * 128 + co + 4] = make_float4(acc[i2][4], acc[i2][5], acc[i2][6], acc[i2][7]);
        }
    }
}

// ---------------- aggregation + bias + rational (warp per node) ----------------
__global__ void agg_kernel(const float* __restrict__ bvec,
                           const float* __restrict__ rat_num,
                           const float* __restrict__ rat_den,
                           const int* __restrict__ assign,
                           int useR) {
    __shared__ float s_num[CLUST * 6];
    __shared__ float s_den[CLUST * 4];
    int tid = threadIdx.x;
    if (tid < CLUST * 6) s_num[tid] = rat_num[tid];
    if (tid < CLUST * 4) s_den[tid] = rat_den[tid];
    __syncthreads();
    int lane = tid & 31;
    int v = (blockIdx.x * blockDim.x + tid) >> 5;
    if (v >= Nn) return;
    float dv = g_dinv[v];
    int beg = g_rowptr[v], end = g_rowptr[v + 1];
    float4 acc = make_float4(0.f, 0.f, 0.f, 0.f);
    const int2* pk = (const int2*)g_csr;
    for (int base = beg; base < end; base += 32) {
        int2 my = make_int2(0, 0);
        if (base + lane < end) my = pk[base + lane];
        int m = min(32, end - base);
        for (int k = 0; k < m; k++) {
            int s = __shfl_sync(0xffffffffu, my.x, k);
            float w = __int_as_float(__shfl_sync(0xffffffffu, my.y, k));
            float cf = dv * w;
            float4 hv = *(const float4*)&g_h[s * 128 + lane * 4];
            acc.x = fmaf(cf, hv.x, acc.x);
            acc.y = fmaf(cf, hv.y, acc.y);
            acc.z = fmaf(cf, hv.z, acc.z);
            acc.w = fmaf(cf, hv.w, acc.w);
        }
    }
    {
        float dv2 = dv * dv;
        float4 hs = *(const float4*)&g_h[v * 128 + lane * 4];
        acc.x = fmaf(dv2, hs.x, acc.x);
        acc.y = fmaf(dv2, hs.y, acc.y);
        acc.z = fmaf(dv2, hs.z, acc.z);
        acc.w = fmaf(dv2, hs.w, acc.w);
    }
    if (useR) {
        float tv = g_t[v];
        float4 rr = *(const float4*)&g_r[lane * 4];
        acc.x = fmaf(tv, rr.x, acc.x);
        acc.y = fmaf(tv, rr.y, acc.y);
        acc.z = fmaf(tv, rr.z, acc.z);
        acc.w = fmaf(tv, rr.w, acc.w);
    }
    {
        float4 bb = *(const float4*)&bvec[lane * 4];
        acc.x += bb.x; acc.y += bb.y; acc.z += bb.z; acc.w += bb.w;
    }
    float z[4] = {acc.x, acc.y, acc.z, acc.w};
    float out[4];
    #pragma unroll
    for (int c = 0; c < 4; c++) {
        int j = lane * 4 + c;
        int cl = assign[j];
        const float* a = &s_num[cl * 6];
        const float* q = &s_den[cl * 4];
        float xx = z[c];
        float P = a[5];
        P = fmaf(P, xx, a[4]); P = fmaf(P, xx, a[3]); P = fmaf(P, xx, a[2]);
        P = fmaf(P, xx, a[1]); P = fmaf(P, xx, a[0]);
        float Q = q[3];
        Q = fmaf(Q, xx, q[2]); Q = fmaf(Q, xx, q[1]); Q = fmaf(Q, xx, q[0]);
        Q *= xx;
        out[c] = P / (1.0f + fabsf(Q));
    }
    *(float4*)&g_act[v * 128 + lane * 4] = make_float4(out[0], out[1], out[2], out[3]);
}

// ---------------- per-feature stats over act ----------------
__global__ void stats_kernel() {
    int j = threadIdx.x & 127;
    int rpb = blockDim.x >> 7; // 2
    int n0 = blockIdx.x * rpb + (threadIdx.x >> 7);
    int stride = gridDim.x * rpb;
    float s = 0.f, sq = 0.f;
    for (int n = n0; n < Nn; n += stride) {
        float v = g_act[n * 128 + j];
        s += v;
        sq = fmaf(v, v, sq);
    }
    atomicAdd(&g_sum[j], s);
    atomicAdd(&g_sq[j], sq);
}

// ---------------- BN affine (a,c); also reset stats ----------------
__global__ void affine_kernel(const float* __restrict__ gw, const float* __restrict__ be) {
    int j = threadIdx.x;
    float mean = g_sum[j] * (1.0f / (float)Nn);
    float var = g_sq[j] * (1.0f / (float)Nn) - mean * mean;
    float a = gw[j] * rsqrtf(var + EPSv);
    g_a[j] = a;
    g_c[j] = be[j] - mean * a;
    g_sum[j] = 0.f;
    g_sq[j] = 0.f;
}

// ---------------- prep next layer: Wa = a*W (row-scale), r = c @ W ----------------
__global__ void prep_kernel(const float* __restrict__ W) {
    int j = threadIdx.x; // 128 threads, 1 block
    float s = 0.f;
    for (int k = 0; k < 128; k++) {
        float w = W[k * 128 + j];
        s = fmaf(g_c[k], w, s);
        g_Wa[k * 128 + j] = g_a[k] * w;
    }
    g_r[j] = s;
}

// ---------------- graph boundaries (batch is sorted) ----------------
__global__ void gstart_kernel(const int* __restrict__ batch) {
    int g = blockIdx.x * blockDim.x + threadIdx.x;
    if (g > Gg) return;
    int lo = 0, hi = Nn;
    while (lo < hi) { int mid = (lo + hi) >> 1; if (batch[mid] < g) lo = mid + 1; else hi = mid; }
    g_gstart[g] = lo;
}

// ---------------- pooling (with layer-3 BN affine applied) ----------------
__global__ void pool_kernel() {
    int g = blockIdx.x, j = threadIdx.x;
    int s = g_gstart[g], e = g_gstart[g + 1];
    float acc = 0.f;
    for (int n = s; n < e; n++) acc += g_act[n * 128 + j];
    float out = 0.f;
    if (e > s) out = fmaf(g_a[j], acc / (float)(e - s), g_c[j]);
    g_pooled[g * 128 + j] = out;
}

// ---------------- MLP head ----------------
__global__ void mlp_kernel(const float* __restrict__ W, const float* __restrict__ bias, int stage) {
    __shared__ float srow[128];
    int g = blockIdx.x, j = threadIdx.x;
    const float* in = (stage == 1) ? g_pooled : g_z1;
    float* out = (stage == 1) ? g_z1 : g_z2;
    srow[j] = in[g * 128 + j];
    __syncthreads();
    float s = bias[j];
    #pragma unroll 8
    for (int k = 0; k < 128; k++) s = fmaf(srow[k], W[k * 128 + j], s);
    s = 0.5f * s * (1.0f + erff(s * 0.70710678118654752f));
    out[g * 128 + j] = s;
}

__global__ void mlp3_kernel(const float* __restrict__ W, const float* __restrict__ bias,
                            float* __restrict__ out) {
    __shared__ float srow[128];
    int g = blockIdx.x, j = threadIdx.x;
    srow[j] = g_z2[g * 128 + j];
    __syncthreads();
    if (j < OUTD) {
        float s = bias[j];
        #pragma unroll 8
        for (int k = 0; k < 128; k++) s = fmaf(srow[k], W[k * OUTD + j], s);
        out[g * OUTD + j] = s;
    }
}

// ---------------- host launch ----------------
extern "C" void kernel_launch(void* const* d_in, const int* in_sizes, int n_in,
                              void* d_out, int out_size) {
    (void)in_sizes; (void)n_in; (void)out_size;
    const float* x       = (const float*)d_in[0];
    const int*   ei      = (const int*)d_in[1];
    const int*   batch   = (const int*)d_in[2];
    const float* W[4]    = {(const float*)d_in[3],  (const float*)d_in[7],
                            (const float*)d_in[11], (const float*)d_in[15]};
    const float* bv[4]   = {(const float*)d_in[4],  (const float*)d_in[8],
                            (const float*)d_in[12], (const float*)d_in[16]};
    const float* gv[4]   = {(const float*)d_in[5],  (const float*)d_in[9],
                            (const float*)d_in[13], (const float*)d_in[17]};
    const float* bev[4]  = {(const float*)d_in[6],  (const float*)d_in[10],
                            (const float*)d_in[14], (const float*)d_in[18]};
    const float* rat_num = (const float*)d_in[19];
    const float* rat_den = (const float*)d_in[20];
    const int*   assign  = (const int*)d_in[21];
    const float* HW1     = (const float*)d_in[22];
    const float* Hb1     = (const float*)d_in[23];
    const float* HW2     = (const float*)d_in[24];
    const float* Hb2     = (const float*)d_in[25];
    const float* HW3     = (const float*)d_in[26];
    const float* Hb3     = (const float*)d_in[27];
    float* out = (float*)d_out;

    const int TB = 256;
    const int nBlocksN = (Nn + TB - 1) / TB;         // 196
    const int nBlocksE = (Ee + TB - 1) / TB;         // 3125
    const int nBlocksWarp = (Nn * 32 + TB - 1) / TB; // 6250
    const int nBlocksGemm = (Nn + 127) / 128;        // 391

    // ---- precompute graph structure (once per launch) ----
    init_kernel<<<nBlocksN, TB>>>();
    hist_kernel<<<nBlocksE, TB>>>(ei);
    scan_kernel<<<1, 1024>>>();
    dinv_kernel<<<nBlocksN, TB>>>();
    fill_kernel<<<nBlocksE, TB>>>(ei);
    pack_kernel<<<nBlocksE, TB>>>();
    tfac_kernel<<<nBlocksWarp, TB>>>();

    // ---- layer 0 ----
    gemm0_kernel<<<1024, TB>>>(x, W[0]);
    agg_kernel<<<nBlocksWarp, TB>>>(bv[0], rat_num, rat_den, assign, 0);
    stats_kernel<<<512, TB>>>();
    affine_kernel<<<1, 128>>>(gv[0], bev[0]);

    // ---- layers 1..3 (BN of previous layer folded into W) ----
    for (int i = 1; i < 4; i++) {
        prep_kernel<<<1, 128>>>(W[i]);
        gemm_kernel<<<nBlocksGemm, 256>>>();
        agg_kernel<<<nBlocksWarp, TB>>>(bv[i], rat_num, rat_den, assign, 1);
        stats_kernel<<<512, TB>>>();
        affine_kernel<<<1, 128>>>(gv[i], bev[i]);
    }

    // ---- pooling + MLP head ----
    gstart_kernel<<<1, 512>>>(batch);
    pool_kernel<<<Gg, 128>>>();
    mlp_kernel<<<Gg, 128>>>(HW1, Hb1, 1);
    mlp_kernel<<<Gg, 128>>>(HW2, Hb2, 2);
    mlp3_kernel<<<Gg, 128>>>(HW3, Hb3, out);
}

// round 8
// speedup vs baseline: 1.0074x; 1.0074x over previous
#include <cuda_runtime.h>
#include <math.h>

// Problem constants
#define Nn 50000
#define Ee 800000
#define IND 9
#define HIDD 128
#define Gg 256
#define OUTD 10
#define CLUST 20
#define EPSv 1e-5f

// ---------------- scratch (device globals; no allocation allowed) ----------------
__device__ float g_h[Nn * HIDD];        // GEMM output (pre-aggregation)
__device__ float g_act[Nn * HIDD];      // rational output (pre-BN)
__device__ int   g_cnt[Nn];
__device__ int   g_cursor[Nn];
__device__ int   g_rowptr[Nn + 1];
__device__ int   g_csr[2 * Ee];         // packed per sorted edge: (src, bits(dinv[src]))
__device__ float g_dinv[Nn];
__device__ float g_t[Nn];
__device__ float g_sum[HIDD];
__device__ float g_sq[HIDD];
__device__ float g_Wa[HIDD * HIDD];
__device__ float g_r[HIDD];
__device__ float g_pooled[Gg * HIDD];
__device__ float g_z1[Gg * HIDD];
__device__ float g_z2[Gg * HIDD];

// ---------------- f32x2 packed-FMA helpers (FFMA2 path, ptxas won't emit it) --------
__device__ __forceinline__ unsigned long long pack2_dup(float x) {
    unsigned long long r;
    asm("mov.b64 %0, {%1, %1};" : "=l"(r) : "f"(x));
    return r;
}
__device__ __forceinline__ void ffma2(unsigned long long& d, unsigned long long a,
                                      unsigned long long b) {
    asm("fma.rn.f32x2 %0, %1, %2, %0;" : "+l"(d) : "l"(a), "l"(b));
}

// ---------------- precompute kernels ----------------
__global__ void init_kernel() {
    int i = blockIdx.x * blockDim.x + threadIdx.x;
    if (i < Nn) { g_cnt[i] = 0; g_cursor[i] = 0; }
    if (i < HIDD) { g_sum[i] = 0.f; g_sq[i] = 0.f; }
}

__global__ void hist_kernel(const int* __restrict__ ei) {
    int e = blockIdx.x * blockDim.x + threadIdx.x;
    if (e < Ee) atomicAdd(&g_cnt[ei[Ee + e]], 1);
}

// single-block exclusive scan of g_cnt -> g_rowptr, also computes dinv
__global__ void scan_kernel() {
    __shared__ int ssum[1024];
    const int ITEMS = 49; // 1024*49 >= 50000
    int t = threadIdx.x;
    int base = t * ITEMS;
    int s = 0;
    for (int i = 0; i < ITEMS; i++) { int idx = base + i; if (idx < Nn) s += g_cnt[idx]; }
    ssum[t] = s; __syncthreads();
    for (int off = 1; off < 1024; off <<= 1) {
        int v = (t >= off) ? ssum[t - off] : 0;
        __syncthreads();
        ssum[t] += v;
        __syncthreads();
    }
    int run = ssum[t] - s; // exclusive prefix
    for (int i = 0; i < ITEMS; i++) {
        int idx = base + i;
        if (idx < Nn) {
            int c = g_cnt[idx];
            g_rowptr[idx] = run;
            run += c;
            g_dinv[idx] = rsqrtf((float)c + 1.0f);
        }
    }
    if (t == 0) g_rowptr[Nn] = Ee;
}

// fill CSR: write (src, bits(dinv[src])) in one 8B store
__global__ void fill_kernel(const int* __restrict__ ei) {
    int e = blockIdx.x * blockDim.x + threadIdx.x;
    if (e < Ee) {
        int s = ei[e];
        int d = ei[Ee + e];
        int pos = g_rowptr[d] + atomicAdd(&g_cursor[d], 1);
        ((int2*)g_csr)[pos] = make_int2(s, __float_as_int(g_dinv[s]));
    }
}

// ---------------- GEMM layer 0: h = x(N,9) @ W0(9,128) ----------------
__global__ void gemm0_kernel(const float* __restrict__ x, const float* __restrict__ W0) {
    __shared__ float sW[IND * HIDD];
    for (int i = threadIdx.x; i < IND * HIDD; i += blockDim.x) sW[i] = W0[i];
    __syncthreads();
    int j = threadIdx.x & 127;
    int rpb = blockDim.x >> 7; // 2
    int r0 = blockIdx.x * rpb + (threadIdx.x >> 7);
    for (int n = r0; n < Nn; n += gridDim.x * rpb) {
        float acc = 0.f;
        #pragma unroll
        for (int k = 0; k < IND; k++) acc = fmaf(x[n * IND + k], sW[k * HIDD + j], acc);
        g_h[n * HIDD + j] = acc;
    }
}

// ---------------- SGEMM (f32x2 packed): g_h = g_act(N,128) @ g_Wa(128,128) ----------
#define GBK 32
__global__ __launch_bounds__(256, 2) void gemm_kernel() {
    __shared__ float Ast[GBK * 132]; // transposed A chunk [k][row], pad 132
    __shared__ float Ws[GBK * 128];  // B chunk [k][j]
    int tid = threadIdx.x;
    int blockRow = blockIdx.x * 128;
    int tx = tid & 15, ty = tid >> 4;
    int ro = ty * 8, co = tx * 8;
    unsigned long long acc[8][4];
    #pragma unroll
    for (int i = 0; i < 8; i++)
        #pragma unroll
        for (int j = 0; j < 4; j++) acc[i][j] = 0ull;
    for (int kc = 0; kc < 128; kc += GBK) {
        #pragma unroll
        for (int i = 0; i < 4; i++) {
            int v = tid + i * 256;       // [0,1024)
            int row = v >> 3, kq = v & 7;
            int grow = blockRow + row;
            float4 val = make_float4(0.f, 0.f, 0.f, 0.f);
            if (grow < Nn) val = *(const float4*)&g_act[grow * 128 + kc + kq * 4];
            Ast[(kq * 4 + 0) * 132 + row] = val.x;
            Ast[(kq * 4 + 1) * 132 + row] = val.y;
            Ast[(kq * 4 + 2) * 132 + row] = val.z;
            Ast[(kq * 4 + 3) * 132 + row] = val.w;
        }
        #pragma unroll
        for (int i = 0; i < 4; i++) {
            int v = tid + i * 256;
            int kk = v >> 5, jq = v & 31;
            *(float4*)&Ws[kk * 128 + jq * 4] = *(const float4*)&g_Wa[(kc + kk) * 128 + jq * 4];
        }
        __syncthreads();
        #pragma unroll
        for (int kk = 0; kk < GBK; kk++) {
            float a[8];
            *(float4*)(a)     = *(float4*)&Ast[kk * 132 + ro];
            *(float4*)(a + 4) = *(float4*)&Ast[kk * 132 + ro + 4];
            ulonglong2 b01 = *(ulonglong2*)&Ws[kk * 128 + co];
            ulonglong2 b23 = *(ulonglong2*)&Ws[kk * 128 + co + 4];
            unsigned long long bp0 = b01.x, bp1 = b01.y, bp2 = b23.x, bp3 = b23.y;
            #pragma unroll
            for (int i2 = 0; i2 < 8; i2++) {
                unsigned long long ap = pack2_dup(a[i2]);
                ffma2(acc[i2][0], ap, bp0);
                ffma2(acc[i2][1], ap, bp1);
                ffma2(acc[i2][2], ap, bp2);
                ffma2(acc[i2][3], ap, bp3);
            }
        }
        __syncthreads();
    }
    #pragma unroll
    for (int i2 = 0; i2 < 8; i2++) {
        int grow = blockRow + ro + i2;
        if (grow < Nn) {
            ulonglong2 o;
            o.x = acc[i2][0]; o.y = acc[i2][1];
            *(ulonglong2*)&g_h[grow * 128 + co] = o;
            o.x = acc[i2][2]; o.y = acc[i2][3];
            *(ulonglong2*)&g_h[grow * 128 + co + 4] = o;
        }
    }
}

// ------- aggregation + bias + rational + fused BN stats (+optional tfac) -----------
// 8 warps per block, one node per warp. 6250 blocks cover all 50000 nodes exactly.
__global__ __launch_bounds__(256) void agg_kernel(const float* __restrict__ bvec,
                           const float* __restrict__ rat_num,
                           const float* __restrict__ rat_den,
                           const int* __restrict__ assign,
                           int useR, int computeT) {
    __shared__ float s_num[CLUST * 6];
    __shared__ float s_den[CLUST * 4];
    __shared__ float sp_sum[8 * HIDD];
    __shared__ float sp_sq[8 * HIDD];
    int tid = threadIdx.x;
    if (tid < CLUST * 6) s_num[tid] = rat_num[tid];
    if (tid < CLUST * 4) s_den[tid] = rat_den[tid];
    __syncthreads();
    int lane = tid & 31;
    int wid = tid >> 5;
    int v = blockIdx.x * 8 + wid;
    float dv = g_dinv[v];
    int beg = g_rowptr[v], end = g_rowptr[v + 1];
    float4 acc = make_float4(0.f, 0.f, 0.f, 0.f);
    float sw = 0.f;
    const int2* pk = (const int2*)g_csr;
    for (int base = beg; base < end; base += 32) {
        int2 my = make_int2(0, 0);
        if (base + lane < end) my = pk[base + lane];
        sw += __int_as_float(my.y);
        int m = min(32, end - base);
        for (int k = 0; k < m; k++) {
            int s = __shfl_sync(0xffffffffu, my.x, k);
            float w = __int_as_float(__shfl_sync(0xffffffffu, my.y, k));
            float cf = dv * w;
            float4 hv = *(const float4*)&g_h[s * 128 + lane * 4];
            acc.x = fmaf(cf, hv.x, acc.x);
            acc.y = fmaf(cf, hv.y, acc.y);
            acc.z = fmaf(cf, hv.z, acc.z);
            acc.w = fmaf(cf, hv.w, acc.w);
        }
    }
    if (computeT) {
        #pragma unroll
        for (int o = 16; o; o >>= 1) sw += __shfl_xor_sync(0xffffffffu, sw, o);
        if (lane == 0) g_t[v] = dv * sw + dv * dv;
    }
    {
        float dv2 = dv * dv;
        float4 hs = *(const float4*)&g_h[v * 128 + lane * 4];
        acc.x = fmaf(dv2, hs.x, acc.x);
        acc.y = fmaf(dv2, hs.y, acc.y);
        acc.z = fmaf(dv2, hs.z, acc.z);
        acc.w = fmaf(dv2, hs.w, acc.w);
    }
    if (useR) {
        float tv = g_t[v];
        float4 rr = *(const float4*)&g_r[lane * 4];
        acc.x = fmaf(tv, rr.x, acc.x);
        acc.y = fmaf(tv, rr.y, acc.y);
        acc.z = fmaf(tv, rr.z, acc.z);
        acc.w = fmaf(tv, rr.w, acc.w);
    }
    {
        float4 bb = *(const float4*)&bvec[lane * 4];
        acc.x += bb.x; acc.y += bb.y; acc.z += bb.z; acc.w += bb.w;
    }
    float z[4] = {acc.x, acc.y, acc.z, acc.w};
    float out[4];
    #pragma unroll
    for (int c = 0; c < 4; c++) {
        int j = lane * 4 + c;
        int cl = assign[j];
        const float* a = &s_num[cl * 6];
        const float* q = &s_den[cl * 4];
        float xx = z[c];
        float P = a[5];
        P = fmaf(P, xx, a[4]); P = fmaf(P, xx, a[3]); P = fmaf(P, xx, a[2]);
        P = fmaf(P, xx, a[1]); P = fmaf(P, xx, a[0]);
        float Q = q[3];
        Q = fmaf(Q, xx, q[2]); Q = fmaf(Q, xx, q[1]); Q = fmaf(Q, xx, q[0]);
        Q *= xx;
        out[c] = P / (1.0f + fabsf(Q));
        sp_sum[wid * HIDD + j] = out[c];
        sp_sq[wid * HIDD + j]  = out[c] * out[c];
    }
    *(float4*)&g_act[v * 128 + lane * 4] = make_float4(out[0], out[1], out[2], out[3]);
    __syncthreads();
    if (tid < HIDD) {
        float s = 0.f, q = 0.f;
        #pragma unroll
        for (int w = 0; w < 8; w++) {
            s += sp_sum[w * HIDD + tid];
            q += sp_sq[w * HIDD + tid];
        }
        atomicAdd(&g_sum[tid], s);
        atomicAdd(&g_sq[tid], q);
    }
}

// ---- fused: BN affine of previous layer + fold into next layer weights ----
// Wa[k,j] = a[k]*W[k,j];  r[j] = sum_k c[k]*W[k,j]. Also resets stats.
__global__ void affine_prep_kernel(const float* __restrict__ gw,
                                   const float* __restrict__ be,
                                   const float* __restrict__ W) {
    __shared__ float sa[HIDD], sc[HIDD];
    int j = threadIdx.x; // 128 threads, 1 block
    float mean = g_sum[j] * (1.0f / (float)Nn);
    float var = g_sq[j] * (1.0f / (float)Nn) - mean * mean;
    float a = gw[j] * rsqrtf(var + EPSv);
    float c = be[j] - mean * a;
    sa[j] = a; sc[j] = c;
    g_sum[j] = 0.f;
    g_sq[j] = 0.f;
    __syncthreads();
    float s = 0.f;
    #pragma unroll 4
    for (int k = 0; k < HIDD; k++) {
        float w = W[k * HIDD + j];
        s = fmaf(sc[k], w, s);
        g_Wa[k * HIDD + j] = sa[k] * w;
    }
    g_r[j] = s;
}

// ---------------- pooling (inline group boundaries + final-layer BN affine) --------
__global__ void pool_kernel(const float* __restrict__ gw, const float* __restrict__ be,
                            const int* __restrict__ batch) {
    __shared__ int s_se[2];
    int g = blockIdx.x, j = threadIdx.x;
    if (j < 2) {
        int target = g + j;
        int lo = 0, hi = Nn;
        while (lo < hi) { int mid = (lo + hi) >> 1; if (batch[mid] < target) lo = mid + 1; else hi = mid; }
        s_se[j] = lo;
    }
    __syncthreads();
    int s = s_se[0], e = s_se[1];
    float mean = g_sum[j] * (1.0f / (float)Nn);
    float var = g_sq[j] * (1.0f / (float)Nn) - mean * mean;
    float a = gw[j] * rsqrtf(var + EPSv);
    float c = be[j] - mean * a;
    float acc = 0.f;
    for (int n = s; n < e; n++) acc += g_act[n * 128 + j];
    float out = 0.f;
    if (e > s) out = fmaf(a, acc / (float)(e - s), c);
    g_pooled[g * 128 + j] = out;
}

// ---------------- MLP head ----------------
__global__ void mlp_kernel(const float* __restrict__ W, const float* __restrict__ bias, int stage) {
    __shared__ float srow[128];
    int g = blockIdx.x, j = threadIdx.x;
    const float* in = (stage == 1) ? g_pooled : g_z1;
    float* out = (stage == 1) ? g_z1 : g_z2;
    srow[j] = in[g * 128 + j];
    __syncthreads();
    float s = bias[j];
    #pragma unroll 8
    for (int k = 0; k < 128; k++) s = fmaf(srow[k], W[k * 128 + j], s);
    s = 0.5f * s * (1.0f + erff(s * 0.70710678118654752f));
    out[g * 128 + j] = s;
}

__global__ void mlp3_kernel(const float* __restrict__ W, const float* __restrict__ bias,
                            float* __restrict__ out) {
    __shared__ float srow[128];
    int g = blockIdx.x, j = threadIdx.x;
    srow[j] = g_z2[g * 128 + j];
    __syncthreads();
    if (j < OUTD) {
        float s = bias[j];
        #pragma unroll 8
        for (int k = 0; k < 128; k++) s = fmaf(srow[k], W[k * OUTD + j], s);
        out[g * OUTD + j] = s;
    }
}

// ---------------- host launch ----------------
extern "C" void kernel_launch(void* const* d_in, const int* in_sizes, int n_in,
                              void* d_out, int out_size) {
    (void)in_sizes; (void)n_in; (void)out_size;
    const float* x       = (const float*)d_in[0];
    const int*   ei      = (const int*)d_in[1];
    const int*   batch   = (const int*)d_in[2];
    const float* W[4]    = {(const float*)d_in[3],  (const float*)d_in[7],
                            (const float*)d_in[11], (const float*)d_in[15]};
    const float* bv[4]   = {(const float*)d_in[4],  (const float*)d_in[8],
                            (const float*)d_in[12], (const float*)d_in[16]};
    const float* gv[4]   = {(const float*)d_in[5],  (const float*)d_in[9],
                            (const float*)d_in[13], (const float*)d_in[17]};
    const float* bev[4]  = {(const float*)d_in[6],  (const float*)d_in[10],
                            (const float*)d_in[14], (const float*)d_in[18]};
    const float* rat_num = (const float*)d_in[19];
    const float* rat_den = (const float*)d_in[20];
    const int*   assign  = (const int*)d_in[21];
    const float* HW1     = (const float*)d_in[22];
    const float* Hb1     = (const float*)d_in[23];
    const float* HW2     = (const float*)d_in[24];
    const float* Hb2     = (const float*)d_in[25];
    const float* HW3     = (const float*)d_in[26];
    const float* Hb3     = (const float*)d_in[27];
    float* out = (float*)d_out;

    const int TB = 256;
    const int nBlocksN = (Nn + TB - 1) / TB;         // 196
    const int nBlocksE = (Ee + TB - 1) / TB;         // 3125
    const int nBlocksAgg = Nn / 8;                   // 6250 (exact)
    const int nBlocksGemm = (Nn + 127) / 128;        // 391

    // ---- graph structure (per launch; deterministic) ----
    init_kernel<<<nBlocksN, TB>>>();
    hist_kernel<<<nBlocksE, TB>>>(ei);
    scan_kernel<<<1, 1024>>>();                       // + dinv
    fill_kernel<<<nBlocksE, TB>>>(ei);                // + pack

    // ---- layer 0 ----
    gemm0_kernel<<<1024, TB>>>(x, W[0]);
    agg_kernel<<<nBlocksAgg, TB>>>(bv[0], rat_num, rat_den, assign, 0, 1); // + stats + tfac

    // ---- layers 1..3 (BN of previous layer folded into W) ----
    for (int i = 1; i < 4; i++) {
        affine_prep_kernel<<<1, 128>>>(gv[i - 1], bev[i - 1], W[i]);
        gemm_kernel<<<nBlocksGemm, 256>>>();
        agg_kernel<<<nBlocksAgg, TB>>>(bv[i], rat_num, rat_den, assign, 1, 0); // + stats
    }

    // ---- pooling (inline final BN affine + group boundaries) + MLP head ----
    pool_kernel<<<Gg, 128>>>(gv[3], bev[3], batch);
    mlp_kernel<<<Gg, 128>>>(HW1, Hb1, 1);
    mlp_kernel<<<Gg, 128>>>(HW2, Hb2, 2);
    mlp3_kernel<<<Gg, 128>>>(HW3, Hb3, out);
}